// round 3
// baseline (speedup 1.0000x reference)
#include <cuda_runtime.h>

constexpr int SZ    = 512 * 512;
constexpr int O_APW = 0;                      // A^2..A^1024 (10 mats)
constexpr int O_W   = O_APW + 10 * SZ;        // W: 512x2048
constexpr int O_P   = O_W + 512 * 2048;       // chunk partials: 256x512
constexpr int O_FC  = O_P + 256 * 512;        // fold chain: 8 levels x 128 x 512
constexpr int O_V   = O_FC + 8 * 128 * 512;   // 306 weighted vectors (256)
constexpr int O_UAC = O_V + 306 * 256;        // u_t accumulator
constexpr int G_TOT = O_UAC + 256;

__device__ __align__(16) float g_s[G_TOT];

__global__ void k_zero() {
  int i = blockIdx.x * blockDim.x + threadIdx.x;
  if (i < G_TOT / 4) ((float4*)g_s)[i] = make_float4(0.f, 0.f, 0.f, 0.f);
}

__global__ void k_copyB(const float* __restrict__ B) {
  int i = blockIdx.x * blockDim.x + threadIdx.x;
  if (i < 512 * 256) g_s[O_W + (i >> 8) * 2048 + 1792 + (i & 255)] = B[i];
}

// C[M,N] += A[M,K]@B[K,N], row-major, 64x64 tile, split-K via z, atomicAdd.
__global__ void __launch_bounds__(256) k_gemm_nn(
    const float* __restrict__ A, int lda, const float* __restrict__ B, int ldb,
    float* __restrict__ C, int ldc, int kslice)
{
  __shared__ float As[16][64], Bs[16][64];
  const int tid = threadIdx.x, bn = blockIdx.x * 64, bm = blockIdx.y * 64;
  const int k0 = blockIdx.z * kslice;
  const int lr = tid >> 2, lk = (tid & 3) << 2;
  const int br = tid >> 4, bc = (tid & 15) << 2;
  const int tr = (tid >> 4) << 2, tc = (tid & 15) << 2;
  float acc[4][4] = {};
  for (int kt = k0; kt < k0 + kslice; kt += 16) {
    float4 av = *(const float4*)(A + (bm + lr) * lda + kt + lk);
    float4 bv = *(const float4*)(B + (kt + br) * ldb + bn + bc);
    As[lk + 0][lr] = av.x; As[lk + 1][lr] = av.y;
    As[lk + 2][lr] = av.z; As[lk + 3][lr] = av.w;
    *(float4*)&Bs[br][bc] = bv;
    __syncthreads();
#pragma unroll
    for (int kk = 0; kk < 16; kk++) {
      float4 a4 = *(const float4*)&As[kk][tr];
      float4 b4 = *(const float4*)&Bs[kk][tc];
      float ar[4] = {a4.x, a4.y, a4.z, a4.w}, br_[4] = {b4.x, b4.y, b4.z, b4.w};
#pragma unroll
      for (int i = 0; i < 4; i++)
#pragma unroll
        for (int j = 0; j < 4; j++) acc[i][j] += ar[i] * br_[j];
    }
    __syncthreads();
  }
#pragma unroll
  for (int i = 0; i < 4; i++)
#pragma unroll
    for (int j = 0; j < 4; j++)
      atomicAdd(&C[(bm + tr + i) * ldc + bn + tc + j], acc[i][j]);
}

// C[M,N] += A[M,K]@B[N,K]^T; optional addsrc added once (z==0 slice).
__global__ void __launch_bounds__(256) k_gemm_nt(
    const float* __restrict__ A, int lda, const float* __restrict__ B, int ldb,
    float* __restrict__ C, int ldc, int kslice,
    const float* __restrict__ addsrc, int ldadd)
{
  __shared__ float As[16][64], Bs[16][64];
  const int tid = threadIdx.x, bn = blockIdx.x * 64, bm = blockIdx.y * 64;
  const int k0 = blockIdx.z * kslice;
  const int lr = tid >> 2, lk = (tid & 3) << 2;
  const int tr = (tid >> 4) << 2, tc = (tid & 15) << 2;
  float acc[4][4] = {};
  for (int kt = k0; kt < k0 + kslice; kt += 16) {
    float4 av = *(const float4*)(A + (bm + lr) * lda + kt + lk);
    float4 bv = *(const float4*)(B + (bn + lr) * ldb + kt + lk);
    As[lk + 0][lr] = av.x; As[lk + 1][lr] = av.y;
    As[lk + 2][lr] = av.z; As[lk + 3][lr] = av.w;
    Bs[lk + 0][lr] = bv.x; Bs[lk + 1][lr] = bv.y;
    Bs[lk + 2][lr] = bv.z; Bs[lk + 3][lr] = bv.w;
    __syncthreads();
#pragma unroll
    for (int kk = 0; kk < 16; kk++) {
      float4 a4 = *(const float4*)&As[kk][tr];
      float4 b4 = *(const float4*)&Bs[kk][tc];
      float ar[4] = {a4.x, a4.y, a4.z, a4.w}, br_[4] = {b4.x, b4.y, b4.z, b4.w};
#pragma unroll
      for (int i = 0; i < 4; i++)
#pragma unroll
        for (int j = 0; j < 4; j++) acc[i][j] += ar[i] * br_[j];
    }
    __syncthreads();
  }
  if (addsrc && blockIdx.z == 0) {
#pragma unroll
    for (int i = 0; i < 4; i++)
#pragma unroll
      for (int j = 0; j < 4; j++)
        acc[i][j] += addsrc[(bm + tr + i) * ldadd + bn + tc + j];
  }
#pragma unroll
  for (int i = 0; i < 4; i++)
#pragma unroll
    for (int j = 0; j < 4; j++)
      atomicAdd(&C[(bm + tr + i) * ldc + bn + tc + j], acc[i][j]);
}

// Build 306 weighted vectors (weights folded in).
__global__ void k_prep(const float* __restrict__ ynh, const float* __restrict__ phi,
                       const float* __restrict__ pht, const float* __restrict__ sigma,
                       const float* __restrict__ lam)
{
  const int x = blockIdx.x, p = threadIdx.x;
  float* V = g_s + O_V;
#define YREV(j) ynh[(2047 - (j)) * 256 + p]
  if (x == 0) {
    V[p] = YREV(0);
  } else if (x < 17) {
    int i = x - 1; float acc = 0.f;
    for (int j = 0; j < 24; j++) acc += pht[j * 16 + i] * YREV(1 + j);
    V[x * 256 + p] = sqrtf(sqrtf(lam[i])) * acc;
  } else if (x < 34) {
    int l = x - 17; float acc = 0.f;
    for (int k = 0; k < 25; k++) acc += phi[k * 17 + l] * YREV(k);
    V[x * 256 + p] = sqrtf(sqrtf(sigma[l])) * acc;
  } else {
    int idx = x - 34, i = idx / 17, l = idx % 17;
    __shared__ float cm[48];
    if (p < 48) {
      int jlo = p > 24 ? p - 24 : 0, jhi = p < 23 ? p : 23;
      float s = 0.f;
      for (int j = jlo; j <= jhi; j++) s += pht[j * 16 + i] * phi[(p - j) * 17 + l];
      cm[p] = s;
    }
    __syncthreads();
    float acc = 0.f;
    for (int m = 0; m < 48; m++) acc += cm[m] * YREV(2 + m);
    V[x * 256 + p] = sqrtf(sqrtf(lam[i])) * sqrtf(sqrtf(sigma[l])) * acc;
  }
#undef YREV
}

// 306 weighted 256x256 matvecs summed into u_t. Warp per (matrix,row).
__global__ void __launch_bounds__(256) k_matvec(
    const float* __restrict__ M, const float* __restrict__ Mbar)
{
  const int task = (blockIdx.x * 256 + threadIdx.x) >> 5;
  const int lane = threadIdx.x & 31;
  const int x = task >> 8, n = task & 255;
  const float* row = (x < 17 ? Mbar + x * 65536 : M + (x - 17) * 65536) + n * 256;
  const float* v = g_s + O_V + x * 256;
  float acc = 0.f;
#pragma unroll
  for (int j = 0; j < 2; j++) {
    float4 a = ((const float4*)row)[lane + 32 * j];
    float4 b = ((const float4*)v)[lane + 32 * j];
    acc += a.x * b.x + a.y * b.y + a.z * b.z + a.w * b.w;
  }
#pragma unroll
  for (int off = 16; off; off >>= 1) acc += __shfl_xor_sync(~0u, acc, off);
  if (lane == 0) atomicAdd(&g_s[O_UAC + n], acc);
}

// y_nat = yh[2047] - C s ; pred = y_nat + C v ; u_t copy.
__global__ void __launch_bounds__(256) k_finish(
    const float* __restrict__ Cm, const float* __restrict__ yh, float* __restrict__ out)
{
  const int r = (blockIdx.x * 256 + threadIdx.x) >> 5;
  const int lane = threadIdx.x & 31;
  const float* crow = Cm + r * 512;
  const float* s = g_s + O_FC + 7 * 128 * 512;   // L7 out row 0
  const float* v = g_s + O_FC + 127 * 512;       // L0 out row 127
  float ds = 0.f, dv = 0.f;
#pragma unroll
  for (int j = 0; j < 16; j++) {
    int k = lane + 32 * j; float c = crow[k];
    ds += c * s[k]; dv += c * v[k];
  }
#pragma unroll
  for (int off = 16; off; off >>= 1) {
    ds += __shfl_xor_sync(~0u, ds, off);
    dv += __shfl_xor_sync(~0u, dv, off);
  }
  if (lane == 0) {
    float yn = yh[2047 * 256 + r] - ds;
    out[r] = yn; out[256 + r] = yn + dv; out[512 + r] = g_s[O_UAC + r];
  }
}

extern "C" void kernel_launch(void* const* d_in, const int* in_sizes, int n_in,
                              void* d_out, int out_size)
{
  const float* A   = (const float*)d_in[0];
  const float* B   = (const float*)d_in[1];
  const float* Cm  = (const float*)d_in[2];
  const float* M   = (const float*)d_in[3];
  const float* Mb  = (const float*)d_in[4];
  const float* sig = (const float*)d_in[5];
  const float* phi = (const float*)d_in[6];
  const float* lam = (const float*)d_in[7];
  const float* pht = (const float*)d_in[8];
  const float* yh  = (const float*)d_in[9];
  const float* uh  = (const float*)d_in[10];
  const float* ynh = (const float*)d_in[11];
  float* out = (float*)d_out;

  void* sym = nullptr;
  cudaGetSymbolAddress(&sym, g_s);
  float* G = (float*)sym;
  float* Apw = G + O_APW;
  float* W   = G + O_W;
  float* P   = G + O_P;
  float* FC  = G + O_FC;

  k_zero<<<(G_TOT / 4 + 255) / 256, 256>>>();
  k_copyB<<<512, 256>>>(B);
  // W block6 = A @ B
  k_gemm_nn<<<dim3(4, 8, 4), 256>>>(A, 512, W + 1792, 2048, W + 1536, 2048, 128);
  // A^2
  k_gemm_nn<<<dim3(8, 8, 4), 256>>>(A, 512, A, 512, Apw, 512, 128);
  // W blocks 4,5 = A^2 @ blocks 6,7
  k_gemm_nn<<<dim3(8, 8, 4), 256>>>(Apw, 512, W + 1536, 2048, W + 1024, 2048, 128);
  // A^4
  k_gemm_nn<<<dim3(8, 8, 4), 256>>>(Apw, 512, Apw, 512, Apw + SZ, 512, 128);
  // W blocks 0..3 = A^4 @ blocks 4..7
  k_gemm_nn<<<dim3(16, 8, 4), 256>>>(Apw + SZ, 512, W + 1024, 2048, W, 2048, 128);
  // A^8 .. A^1024 (indices 2..9)
  for (int j = 2; j <= 9; j++)
    k_gemm_nn<<<dim3(8, 8, 4), 256>>>(Apw + (j - 1) * SZ, 512, Apw + (j - 1) * SZ, 512,
                                      Apw + j * SZ, 512, 128);
  // chunk partials: P(256x512) = U(256x2048) @ W^T
  k_gemm_nt<<<dim3(8, 4, 8), 256>>>(uh, 2048, W, 2048, P, 512, 256, nullptr, 0);
  // fold levels
  for (int l = 0; l < 8; l++) {
    const float* in = (l == 0) ? P : FC + (l - 1) * 128 * 512;
    float* op = FC + l * 128 * 512;
    k_gemm_nt<<<dim3(8, (l == 0 ? 2 : 1), 2), 256>>>(
        in, 1024, Apw + (2 + l) * SZ, 512, op, 512, 256, in + 512, 1024);
  }
  // u_t phase
  k_prep<<<306, 256>>>(ynh, phi, pht, sig, lam);
  k_matvec<<<(306 * 256 * 32) / 256, 256>>>(M, Mb);
  // outputs
  k_finish<<<32, 256>>>(Cm, yh, out);
}